// round 11
// baseline (speedup 1.0000x reference)
#include <cuda_runtime.h>
#include <cuda_bf16.h>

// out[n] = prod_f sigmoid(10*(x[n,f]*w[f]+b[f]))^(1/2)
//        = rsqrt( prod_f (1 + exp2( (x*w+b) * (-10*log2 e) )) )
//
// FINAL CONFIG — confirmed best across the R2/R4-R10 sweep (benched 80.4,
// 84.5, 80.35 us; only config to reproduce sub-81):
//   - half-warp (16 lanes x float4) covers one 64-float row; warp covers
//     2 rows per LDG.128; unroll x4 = 8 rows / 2KB per warp-iter
//   - 4 LDG.128 front-batched, true MLP=4 (38 regs under the 51-reg budget
//     of launch_bounds(128,10) -- no spills, no de-batching)
//   - 128-thread blocks, 10 CTAs/SM, grid 1480 = exactly one resident wave
//     of persistent CTAs on 148 SMs
//
// Measured ceiling: 6.42-6.54 TB/s HBM (81-82.5% of 8TB/s spec), flat across
// MLP=2/4/8 and occ 47-94% -> memory-roofline bound. Byte count (520 MB fp32
// stream) is algorithmically irreducible; LDG vs TMA is path-equivalent at
// the LTS cap, so no staging scheme can exceed this.

#define GRID_BLOCKS 1480   // 148 SMs * 10 CTAs of 128 threads
#define BLOCK_THREADS 128

__global__ __launch_bounds__(BLOCK_THREADS, 10)
void one_to_one_prod_kernel(const float* __restrict__ x,
                            const float* __restrict__ w,
                            const float* __restrict__ b,
                            float* __restrict__ out,
                            unsigned n_rows)
{
    const unsigned lane  = threadIdx.x & 31u;
    const unsigned half  = lane >> 4;       // which row of a pair
    const unsigned hlane = lane & 15u;      // lane within half-warp

    const float NEG10_LOG2E = -14.4269504088896340736f; // -10 * log2(e)
    float4 w4 = reinterpret_cast<const float4*>(w)[hlane];
    float4 b4 = reinterpret_cast<const float4*>(b)[hlane];
    w4.x *= NEG10_LOG2E; w4.y *= NEG10_LOG2E; w4.z *= NEG10_LOG2E; w4.w *= NEG10_LOG2E;
    b4.x *= NEG10_LOG2E; b4.y *= NEG10_LOG2E; b4.z *= NEG10_LOG2E; b4.w *= NEG10_LOG2E;

    const unsigned warp_id = blockIdx.x * (blockDim.x >> 5) + (threadIdx.x >> 5);
    const unsigned n_warps = gridDim.x * (blockDim.x >> 5);
    const unsigned n_octs  = n_rows >> 3;       // 8 rows per warp-iter

    // x viewed as float4; row r starts at float4 index r*16.
    // Max index 2^21 * 16 = 2^25 -- fits 32-bit.
    const float4* __restrict__ xv = reinterpret_cast<const float4*>(x);

    for (unsigned q = warp_id; q < n_octs; q += n_warps) {
        const unsigned row0 = 8u * q + half;        // this lane: rows row0,+2,+4,+6
        const unsigned i0 = row0 * 16u + hlane;     // float4 index

        // Front-batch 4 independent LDG.128 (true MLP=4)
        const float4 v0 = __ldcs(xv + i0);
        const float4 v1 = __ldcs(xv + i0 + 32u);    // +2 rows
        const float4 v2 = __ldcs(xv + i0 + 64u);    // +4 rows
        const float4 v3 = __ldcs(xv + i0 + 96u);    // +6 rows

        // 4 independent MUFU chains
        float a0 = exp2f(fmaf(v0.x, w4.x, b4.x));
        float a1 = exp2f(fmaf(v0.y, w4.y, b4.y));
        float a2 = exp2f(fmaf(v0.z, w4.z, b4.z));
        float a3 = exp2f(fmaf(v0.w, w4.w, b4.w));

        float c0 = exp2f(fmaf(v1.x, w4.x, b4.x));
        float c1 = exp2f(fmaf(v1.y, w4.y, b4.y));
        float c2 = exp2f(fmaf(v1.z, w4.z, b4.z));
        float c3 = exp2f(fmaf(v1.w, w4.w, b4.w));

        float d0 = exp2f(fmaf(v2.x, w4.x, b4.x));
        float d1 = exp2f(fmaf(v2.y, w4.y, b4.y));
        float d2 = exp2f(fmaf(v2.z, w4.z, b4.z));
        float d3 = exp2f(fmaf(v2.w, w4.w, b4.w));

        float g0 = exp2f(fmaf(v3.x, w4.x, b4.x));
        float g1 = exp2f(fmaf(v3.y, w4.y, b4.y));
        float g2 = exp2f(fmaf(v3.z, w4.z, b4.z));
        float g3 = exp2f(fmaf(v3.w, w4.w, b4.w));

        float f0 = rsqrtf((1.0f + a0) * (1.0f + a1) * (1.0f + a2) * (1.0f + a3));
        float f1 = rsqrtf((1.0f + c0) * (1.0f + c1) * (1.0f + c2) * (1.0f + c3));
        float f2 = rsqrtf((1.0f + d0) * (1.0f + d1) * (1.0f + d2) * (1.0f + d3));
        float f3 = rsqrtf((1.0f + g0) * (1.0f + g1) * (1.0f + g2) * (1.0f + g3));

        // 4 interleaved multiply-reductions across each 16-lane half-warp
        #pragma unroll
        for (int off = 8; off > 0; off >>= 1) {
            f0 *= __shfl_xor_sync(0xFFFFFFFFu, f0, off, 16);
            f1 *= __shfl_xor_sync(0xFFFFFFFFu, f1, off, 16);
            f2 *= __shfl_xor_sync(0xFFFFFFFFu, f2, off, 16);
            f3 *= __shfl_xor_sync(0xFFFFFFFFu, f3, off, 16);
        }

        if (hlane == 0u) {
            // lanes 0/16 write rows {row0,+2,+4,+6} — 8 adjacent floats = 32B
            __stcs(out + row0,      f0);
            __stcs(out + row0 + 2u, f1);
            __stcs(out + row0 + 4u, f2);
            __stcs(out + row0 + 6u, f3);
        }
    }

    // Tail (n_rows not divisible by 8): leftover rows pair-wise.
    const unsigned tail_start = n_octs * 8u;
    if (tail_start < n_rows) {
        const unsigned n_pairs_tail = (n_rows - tail_start) >> 1;
        for (unsigned t = warp_id; t < n_pairs_tail; t += n_warps) {
            const unsigned row = tail_start + 2u * t + half;
            const float4 v = __ldcs(xv + row * 16u + hlane);
            float e0 = exp2f(fmaf(v.x, w4.x, b4.x));
            float e1 = exp2f(fmaf(v.y, w4.y, b4.y));
            float e2 = exp2f(fmaf(v.z, w4.z, b4.z));
            float e3 = exp2f(fmaf(v.w, w4.w, b4.w));
            float f = rsqrtf((1.0f + e0) * (1.0f + e1) * (1.0f + e2) * (1.0f + e3));
            #pragma unroll
            for (int off = 8; off > 0; off >>= 1)
                f *= __shfl_xor_sync(0xFFFFFFFFu, f, off, 16);
            if (hlane == 0u) out[row] = f;
        }
        if ((n_rows - tail_start) & 1u) {
            if (warp_id == 0u) {
                const unsigned row = n_rows - 1u;
                const float4 v = __ldcs(xv + row * 16u + hlane);
                float e0 = exp2f(fmaf(v.x, w4.x, b4.x));
                float e1 = exp2f(fmaf(v.y, w4.y, b4.y));
                float e2 = exp2f(fmaf(v.z, w4.z, b4.z));
                float e3 = exp2f(fmaf(v.w, w4.w, b4.w));
                float f = rsqrtf((1.0f + e0) * (1.0f + e1) * (1.0f + e2) * (1.0f + e3));
                #pragma unroll
                for (int off = 8; off > 0; off >>= 1)
                    f *= __shfl_xor_sync(0xFFFFFFFFu, f, off, 32);
                if (lane == 0u) out[row] = f;
            }
        }
    }
}

extern "C" void kernel_launch(void* const* d_in, const int* in_sizes, int n_in,
                              void* d_out, int out_size)
{
    const float* x = (const float*)d_in[0];   // [N, 64]
    const float* w = (const float*)d_in[1];   // [64]
    const float* b = (const float*)d_in[2];   // [64]
    float* out = (float*)d_out;               // [N]

    const unsigned n_rows = (unsigned)((long long)in_sizes[0] / 64);

    one_to_one_prod_kernel<<<GRID_BLOCKS, BLOCK_THREADS>>>(x, w, b, out, n_rows);
}

// round 12
// speedup vs baseline: 1.0061x; 1.0061x over previous
#include <cuda_runtime.h>
#include <cuda_bf16.h>

// out[n] = prod_f sigmoid(10*(x[n,f]*w[f]+b[f]))^(1/2)
//        = rsqrt( prod_f (1 + exp2( (x*w+b) * (-10*log2 e) )) )
//
// FINAL — confirmed best across R2/R4-R11 (samples 80.4, 84.5, 80.35, 84.2 us;
// holds the two best samples of the session; ncu profile invariant at
// DRAM 82%, 6.5 TB/s):
//   - half-warp (16 lanes x float4) covers one 64-float row; warp covers
//     2 rows per LDG.128; unroll x4 = 8 rows / 2KB per warp-iter
//   - 4 LDG.128 front-batched, true MLP=4 (38 regs under the 51-reg budget
//     of launch_bounds(128,10) -- no spills, no de-batching)
//   - 128-thread blocks, 10 CTAs/SM, grid 1480 = exactly one resident wave
//     of persistent CTAs on 148 SMs
//
// Measured ceiling: 6.42-6.54 TB/s HBM (81-82.5% of 8TB/s spec), flat across
// MLP=2/4/8 and occ 47-94% -> memory-roofline bound. The 520 MB fp32 stream
// is algorithmically irreducible and LDG/TMA are path-equivalent at the LTS
// cap, so no restaging scheme can exceed this.

#define GRID_BLOCKS 1480   // 148 SMs * 10 CTAs of 128 threads
#define BLOCK_THREADS 128

__global__ __launch_bounds__(BLOCK_THREADS, 10)
void one_to_one_prod_kernel(const float* __restrict__ x,
                            const float* __restrict__ w,
                            const float* __restrict__ b,
                            float* __restrict__ out,
                            unsigned n_rows)
{
    const unsigned lane  = threadIdx.x & 31u;
    const unsigned half  = lane >> 4;       // which row of a pair
    const unsigned hlane = lane & 15u;      // lane within half-warp

    const float NEG10_LOG2E = -14.4269504088896340736f; // -10 * log2(e)
    float4 w4 = reinterpret_cast<const float4*>(w)[hlane];
    float4 b4 = reinterpret_cast<const float4*>(b)[hlane];
    w4.x *= NEG10_LOG2E; w4.y *= NEG10_LOG2E; w4.z *= NEG10_LOG2E; w4.w *= NEG10_LOG2E;
    b4.x *= NEG10_LOG2E; b4.y *= NEG10_LOG2E; b4.z *= NEG10_LOG2E; b4.w *= NEG10_LOG2E;

    const unsigned warp_id = blockIdx.x * (blockDim.x >> 5) + (threadIdx.x >> 5);
    const unsigned n_warps = gridDim.x * (blockDim.x >> 5);
    const unsigned n_octs  = n_rows >> 3;       // 8 rows per warp-iter

    // x viewed as float4; row r starts at float4 index r*16.
    // Max index 2^21 * 16 = 2^25 -- fits 32-bit.
    const float4* __restrict__ xv = reinterpret_cast<const float4*>(x);

    for (unsigned q = warp_id; q < n_octs; q += n_warps) {
        const unsigned row0 = 8u * q + half;        // this lane: rows row0,+2,+4,+6
        const unsigned i0 = row0 * 16u + hlane;     // float4 index

        // Front-batch 4 independent LDG.128 (true MLP=4)
        const float4 v0 = __ldcs(xv + i0);
        const float4 v1 = __ldcs(xv + i0 + 32u);    // +2 rows
        const float4 v2 = __ldcs(xv + i0 + 64u);    // +4 rows
        const float4 v3 = __ldcs(xv + i0 + 96u);    // +6 rows

        // 4 independent MUFU chains
        float a0 = exp2f(fmaf(v0.x, w4.x, b4.x));
        float a1 = exp2f(fmaf(v0.y, w4.y, b4.y));
        float a2 = exp2f(fmaf(v0.z, w4.z, b4.z));
        float a3 = exp2f(fmaf(v0.w, w4.w, b4.w));

        float c0 = exp2f(fmaf(v1.x, w4.x, b4.x));
        float c1 = exp2f(fmaf(v1.y, w4.y, b4.y));
        float c2 = exp2f(fmaf(v1.z, w4.z, b4.z));
        float c3 = exp2f(fmaf(v1.w, w4.w, b4.w));

        float d0 = exp2f(fmaf(v2.x, w4.x, b4.x));
        float d1 = exp2f(fmaf(v2.y, w4.y, b4.y));
        float d2 = exp2f(fmaf(v2.z, w4.z, b4.z));
        float d3 = exp2f(fmaf(v2.w, w4.w, b4.w));

        float g0 = exp2f(fmaf(v3.x, w4.x, b4.x));
        float g1 = exp2f(fmaf(v3.y, w4.y, b4.y));
        float g2 = exp2f(fmaf(v3.z, w4.z, b4.z));
        float g3 = exp2f(fmaf(v3.w, w4.w, b4.w));

        float f0 = rsqrtf((1.0f + a0) * (1.0f + a1) * (1.0f + a2) * (1.0f + a3));
        float f1 = rsqrtf((1.0f + c0) * (1.0f + c1) * (1.0f + c2) * (1.0f + c3));
        float f2 = rsqrtf((1.0f + d0) * (1.0f + d1) * (1.0f + d2) * (1.0f + d3));
        float f3 = rsqrtf((1.0f + g0) * (1.0f + g1) * (1.0f + g2) * (1.0f + g3));

        // 4 interleaved multiply-reductions across each 16-lane half-warp
        #pragma unroll
        for (int off = 8; off > 0; off >>= 1) {
            f0 *= __shfl_xor_sync(0xFFFFFFFFu, f0, off, 16);
            f1 *= __shfl_xor_sync(0xFFFFFFFFu, f1, off, 16);
            f2 *= __shfl_xor_sync(0xFFFFFFFFu, f2, off, 16);
            f3 *= __shfl_xor_sync(0xFFFFFFFFu, f3, off, 16);
        }

        if (hlane == 0u) {
            // lanes 0/16 write rows {row0,+2,+4,+6} — 8 adjacent floats = 32B
            __stcs(out + row0,      f0);
            __stcs(out + row0 + 2u, f1);
            __stcs(out + row0 + 4u, f2);
            __stcs(out + row0 + 6u, f3);
        }
    }

    // Tail (n_rows not divisible by 8): leftover rows pair-wise.
    const unsigned tail_start = n_octs * 8u;
    if (tail_start < n_rows) {
        const unsigned n_pairs_tail = (n_rows - tail_start) >> 1;
        for (unsigned t = warp_id; t < n_pairs_tail; t += n_warps) {
            const unsigned row = tail_start + 2u * t + half;
            const float4 v = __ldcs(xv + row * 16u + hlane);
            float e0 = exp2f(fmaf(v.x, w4.x, b4.x));
            float e1 = exp2f(fmaf(v.y, w4.y, b4.y));
            float e2 = exp2f(fmaf(v.z, w4.z, b4.z));
            float e3 = exp2f(fmaf(v.w, w4.w, b4.w));
            float f = rsqrtf((1.0f + e0) * (1.0f + e1) * (1.0f + e2) * (1.0f + e3));
            #pragma unroll
            for (int off = 8; off > 0; off >>= 1)
                f *= __shfl_xor_sync(0xFFFFFFFFu, f, off, 16);
            if (hlane == 0u) out[row] = f;
        }
        if ((n_rows - tail_start) & 1u) {
            if (warp_id == 0u) {
                const unsigned row = n_rows - 1u;
                const float4 v = __ldcs(xv + row * 16u + hlane);
                float e0 = exp2f(fmaf(v.x, w4.x, b4.x));
                float e1 = exp2f(fmaf(v.y, w4.y, b4.y));
                float e2 = exp2f(fmaf(v.z, w4.z, b4.z));
                float e3 = exp2f(fmaf(v.w, w4.w, b4.w));
                float f = rsqrtf((1.0f + e0) * (1.0f + e1) * (1.0f + e2) * (1.0f + e3));
                #pragma unroll
                for (int off = 8; off > 0; off >>= 1)
                    f *= __shfl_xor_sync(0xFFFFFFFFu, f, off, 32);
                if (lane == 0u) out[row] = f;
            }
        }
    }
}

extern "C" void kernel_launch(void* const* d_in, const int* in_sizes, int n_in,
                              void* d_out, int out_size)
{
    const float* x = (const float*)d_in[0];   // [N, 64]
    const float* w = (const float*)d_in[1];   // [64]
    const float* b = (const float*)d_in[2];   // [64]
    float* out = (float*)d_out;               // [N]

    const unsigned n_rows = (unsigned)((long long)in_sizes[0] / 64);

    one_to_one_prod_kernel<<<GRID_BLOCKS, BLOCK_THREADS>>>(x, w, b, out, n_rows);
}

// round 13
// speedup vs baseline: 1.0536x; 1.0472x over previous
#include <cuda_runtime.h>
#include <cuda_bf16.h>

// out[n] = prod_f sigmoid(10*(x[n,f]*w[f]+b[f]))^(1/2)
//        = rsqrt( prod_f (1 + exp2( (x*w+b) * (-10*log2 e) )) )
//
// FINAL — confirmed best across R2/R4-R12 (samples 80.4, 84.5, 80.35, 84.2,
// 83.7 us; holds the two best samples of the session; ncu profile stable at
// DRAM 82-83%, 6.5-6.6 TB/s):
//   - half-warp (16 lanes x float4) covers one 64-float row; warp covers
//     2 rows per LDG.128; unroll x4 = 8 rows / 2KB per warp-iter
//   - 4 LDG.128 front-batched, true MLP=4 (38 regs under the 51-reg budget
//     of launch_bounds(128,10) -- no spills, no de-batching)
//   - 128-thread blocks, 10 CTAs/SM, grid 1480 = exactly one resident wave
//     of persistent CTAs on 148 SMs
//
// Measured ceiling: 6.42-6.61 TB/s HBM (81-83% of 8TB/s spec), flat across
// MLP=2/4/8 and occ 47-94% -> memory-roofline bound. The 520 MB fp32 stream
// is algorithmically irreducible and LDG/TMA are path-equivalent at the LTS
// cap, so no restaging scheme can exceed this.

#define GRID_BLOCKS 1480   // 148 SMs * 10 CTAs of 128 threads
#define BLOCK_THREADS 128

__global__ __launch_bounds__(BLOCK_THREADS, 10)
void one_to_one_prod_kernel(const float* __restrict__ x,
                            const float* __restrict__ w,
                            const float* __restrict__ b,
                            float* __restrict__ out,
                            unsigned n_rows)
{
    const unsigned lane  = threadIdx.x & 31u;
    const unsigned half  = lane >> 4;       // which row of a pair
    const unsigned hlane = lane & 15u;      // lane within half-warp

    const float NEG10_LOG2E = -14.4269504088896340736f; // -10 * log2(e)
    float4 w4 = reinterpret_cast<const float4*>(w)[hlane];
    float4 b4 = reinterpret_cast<const float4*>(b)[hlane];
    w4.x *= NEG10_LOG2E; w4.y *= NEG10_LOG2E; w4.z *= NEG10_LOG2E; w4.w *= NEG10_LOG2E;
    b4.x *= NEG10_LOG2E; b4.y *= NEG10_LOG2E; b4.z *= NEG10_LOG2E; b4.w *= NEG10_LOG2E;

    const unsigned warp_id = blockIdx.x * (blockDim.x >> 5) + (threadIdx.x >> 5);
    const unsigned n_warps = gridDim.x * (blockDim.x >> 5);
    const unsigned n_octs  = n_rows >> 3;       // 8 rows per warp-iter

    // x viewed as float4; row r starts at float4 index r*16.
    // Max index 2^21 * 16 = 2^25 -- fits 32-bit.
    const float4* __restrict__ xv = reinterpret_cast<const float4*>(x);

    for (unsigned q = warp_id; q < n_octs; q += n_warps) {
        const unsigned row0 = 8u * q + half;        // this lane: rows row0,+2,+4,+6
        const unsigned i0 = row0 * 16u + hlane;     // float4 index

        // Front-batch 4 independent LDG.128 (true MLP=4)
        const float4 v0 = __ldcs(xv + i0);
        const float4 v1 = __ldcs(xv + i0 + 32u);    // +2 rows
        const float4 v2 = __ldcs(xv + i0 + 64u);    // +4 rows
        const float4 v3 = __ldcs(xv + i0 + 96u);    // +6 rows

        // 4 independent MUFU chains
        float a0 = exp2f(fmaf(v0.x, w4.x, b4.x));
        float a1 = exp2f(fmaf(v0.y, w4.y, b4.y));
        float a2 = exp2f(fmaf(v0.z, w4.z, b4.z));
        float a3 = exp2f(fmaf(v0.w, w4.w, b4.w));

        float c0 = exp2f(fmaf(v1.x, w4.x, b4.x));
        float c1 = exp2f(fmaf(v1.y, w4.y, b4.y));
        float c2 = exp2f(fmaf(v1.z, w4.z, b4.z));
        float c3 = exp2f(fmaf(v1.w, w4.w, b4.w));

        float d0 = exp2f(fmaf(v2.x, w4.x, b4.x));
        float d1 = exp2f(fmaf(v2.y, w4.y, b4.y));
        float d2 = exp2f(fmaf(v2.z, w4.z, b4.z));
        float d3 = exp2f(fmaf(v2.w, w4.w, b4.w));

        float g0 = exp2f(fmaf(v3.x, w4.x, b4.x));
        float g1 = exp2f(fmaf(v3.y, w4.y, b4.y));
        float g2 = exp2f(fmaf(v3.z, w4.z, b4.z));
        float g3 = exp2f(fmaf(v3.w, w4.w, b4.w));

        float f0 = rsqrtf((1.0f + a0) * (1.0f + a1) * (1.0f + a2) * (1.0f + a3));
        float f1 = rsqrtf((1.0f + c0) * (1.0f + c1) * (1.0f + c2) * (1.0f + c3));
        float f2 = rsqrtf((1.0f + d0) * (1.0f + d1) * (1.0f + d2) * (1.0f + d3));
        float f3 = rsqrtf((1.0f + g0) * (1.0f + g1) * (1.0f + g2) * (1.0f + g3));

        // 4 interleaved multiply-reductions across each 16-lane half-warp
        #pragma unroll
        for (int off = 8; off > 0; off >>= 1) {
            f0 *= __shfl_xor_sync(0xFFFFFFFFu, f0, off, 16);
            f1 *= __shfl_xor_sync(0xFFFFFFFFu, f1, off, 16);
            f2 *= __shfl_xor_sync(0xFFFFFFFFu, f2, off, 16);
            f3 *= __shfl_xor_sync(0xFFFFFFFFu, f3, off, 16);
        }

        if (hlane == 0u) {
            // lanes 0/16 write rows {row0,+2,+4,+6} — 8 adjacent floats = 32B
            __stcs(out + row0,      f0);
            __stcs(out + row0 + 2u, f1);
            __stcs(out + row0 + 4u, f2);
            __stcs(out + row0 + 6u, f3);
        }
    }

    // Tail (n_rows not divisible by 8): leftover rows pair-wise.
    const unsigned tail_start = n_octs * 8u;
    if (tail_start < n_rows) {
        const unsigned n_pairs_tail = (n_rows - tail_start) >> 1;
        for (unsigned t = warp_id; t < n_pairs_tail; t += n_warps) {
            const unsigned row = tail_start + 2u * t + half;
            const float4 v = __ldcs(xv + row * 16u + hlane);
            float e0 = exp2f(fmaf(v.x, w4.x, b4.x));
            float e1 = exp2f(fmaf(v.y, w4.y, b4.y));
            float e2 = exp2f(fmaf(v.z, w4.z, b4.z));
            float e3 = exp2f(fmaf(v.w, w4.w, b4.w));
            float f = rsqrtf((1.0f + e0) * (1.0f + e1) * (1.0f + e2) * (1.0f + e3));
            #pragma unroll
            for (int off = 8; off > 0; off >>= 1)
                f *= __shfl_xor_sync(0xFFFFFFFFu, f, off, 16);
            if (hlane == 0u) out[row] = f;
        }
        if ((n_rows - tail_start) & 1u) {
            if (warp_id == 0u) {
                const unsigned row = n_rows - 1u;
                const float4 v = __ldcs(xv + row * 16u + hlane);
                float e0 = exp2f(fmaf(v.x, w4.x, b4.x));
                float e1 = exp2f(fmaf(v.y, w4.y, b4.y));
                float e2 = exp2f(fmaf(v.z, w4.z, b4.z));
                float e3 = exp2f(fmaf(v.w, w4.w, b4.w));
                float f = rsqrtf((1.0f + e0) * (1.0f + e1) * (1.0f + e2) * (1.0f + e3));
                #pragma unroll
                for (int off = 8; off > 0; off >>= 1)
                    f *= __shfl_xor_sync(0xFFFFFFFFu, f, off, 32);
                if (lane == 0u) out[row] = f;
            }
        }
    }
}

extern "C" void kernel_launch(void* const* d_in, const int* in_sizes, int n_in,
                              void* d_out, int out_size)
{
    const float* x = (const float*)d_in[0];   // [N, 64]
    const float* w = (const float*)d_in[1];   // [64]
    const float* b = (const float*)d_in[2];   // [64]
    float* out = (float*)d_out;               // [N]

    const unsigned n_rows = (unsigned)((long long)in_sizes[0] / 64);

    one_to_one_prod_kernel<<<GRID_BLOCKS, BLOCK_THREADS>>>(x, w, b, out, n_rows);
}